// round 1
// baseline (speedup 1.0000x reference)
#include <cuda_runtime.h>

#define NB 10       // n*t batches
#define C  64       // channels
#define HW 16384    // 128*128 spatial
#define K  512      // codebook size
#define NG 32       // groups
#define CPG 2       // channels per group
#define TPB 256     // threads per block (1 token each)

// Scratch for GroupNorm statistics (no cudaMalloc allowed).
__device__ float g_mean[NB * NG];
__device__ float g_rstd[NB * NG];

// ---------------------------------------------------------------------------
// Kernel 1: GroupNorm statistics. One block per (batch, group).
// Each group's data is 2*16384 = 32768 CONTIGUOUS floats in (B,C,H,W) layout.
// ---------------------------------------------------------------------------
__global__ void gn_stats_kernel(const float* __restrict__ x) {
    int bg = blockIdx.x;  // 0..319  == b*NG + g
    const float4* p = (const float4*)(x + (size_t)bg * (CPG * HW));
    const int n4 = (CPG * HW) / 4;  // 8192

    float s = 0.f, ss = 0.f;
    #pragma unroll 4
    for (int i = threadIdx.x; i < n4; i += blockDim.x) {
        float4 v = p[i];
        s  += (v.x + v.y) + (v.z + v.w);
        ss += (v.x * v.x + v.y * v.y) + (v.z * v.z + v.w * v.w);
    }
    // warp reduce
    #pragma unroll
    for (int o = 16; o; o >>= 1) {
        s  += __shfl_xor_sync(0xFFFFFFFFu, s, o);
        ss += __shfl_xor_sync(0xFFFFFFFFu, ss, o);
    }
    __shared__ float sm1[8], sm2[8];
    int w = threadIdx.x >> 5, l = threadIdx.x & 31;
    if (l == 0) { sm1[w] = s; sm2[w] = ss; }
    __syncthreads();
    if (threadIdx.x == 0) {
        float ts = 0.f, tss = 0.f;
        #pragma unroll
        for (int i = 0; i < 8; i++) { ts += sm1[i]; tss += sm2[i]; }
        const float inv = 1.f / (float)(CPG * HW);
        float mean = ts * inv;
        float var  = tss * inv - mean * mean;   // biased var, matches jnp.var
        g_mean[bg] = mean;
        g_rstd[bg] = rsqrtf(var + 1e-6f);
    }
}

// ---------------------------------------------------------------------------
// Kernel 2: fused GN-fold -> phi -> soft-VQ softmax attention -> wz + residual
// One thread per token; codebook + folded weights resident in smem.
// ---------------------------------------------------------------------------
__global__ __launch_bounds__(TPB, 1)
void fused_vq_kernel(const float* __restrict__ x,
                     const float* __restrict__ mb,
                     const float* __restrict__ phi_w,
                     const float* __restrict__ phi_b,
                     const float* __restrict__ gn_w,
                     const float* __restrict__ gn_b,
                     const float* __restrict__ wz_w,
                     const float* __restrict__ wz_b,
                     float* __restrict__ out) {
    extern __shared__ float smem[];
    float* mb_s  = smem;             // C*K   = 32768 floats
    float* pw2   = mb_s + C * K;     // C*C   = 4096  (phi_w with GN scale folded)
    float* wz_s  = pw2 + C * C;      // C*C   = 4096
    float* bias2 = wz_s + C * C;     // C     (phi bias with GN shift folded)
    float* wzb_s = bias2 + C;        // C
    float* scA   = wzb_s + C;        // C
    float* shB   = scA + C;          // C

    const int b   = blockIdx.y;
    const int tid = threadIdx.x;

    // ---- fold GroupNorm affine into per-channel scale/shift ----
    if (tid < C) {
        int g = tid >> 1;                    // CPG = 2
        float mean = g_mean[b * NG + g];
        float rstd = g_rstd[b * NG + g];
        float a = rstd * gn_w[tid];
        scA[tid] = a;
        shB[tid] = gn_b[tid] - mean * a;
        wzb_s[tid] = wz_b[tid];
    }
    __syncthreads();

    // ---- cooperative smem fills ----
    {
        const float4* src = (const float4*)mb;
        float4* dst = (float4*)mb_s;
        #pragma unroll
        for (int i = tid; i < (C * K) / 4; i += TPB) dst[i] = src[i];
    }
    for (int i = tid; i < C * C; i += TPB) {
        pw2[i]  = phi_w[i] * scA[i & (C - 1)];   // fold GN scale into phi
        wz_s[i] = wz_w[i];
    }
    if (tid < C) {
        float acc = phi_b[tid];
        #pragma unroll
        for (int c = 0; c < C; c++) acc += phi_w[tid * C + c] * shB[c];
        bias2[tid] = acc;                        // fold GN shift into phi bias
    }
    __syncthreads();

    const int tok = blockIdx.x * TPB + tid;
    const float* xb = x + (size_t)b * C * HW + tok;

    // ---- phi: p = pw2 @ x_token + bias2, scaled by C^-0.5 = 0.125 ----
    float p[C];
    {
        float xv[C];
        #pragma unroll
        for (int c = 0; c < C; c++) xv[c] = xb[(size_t)c * HW];  // coalesced
        #pragma unroll 4
        for (int o = 0; o < C; o++) {
            float a0 = bias2[o], a1 = 0.f, a2 = 0.f, a3 = 0.f;
            #pragma unroll
            for (int c = 0; c < C; c += 4) {
                a0 += pw2[o * C + c + 0] * xv[c + 0];
                a1 += pw2[o * C + c + 1] * xv[c + 1];
                a2 += pw2[o * C + c + 2] * xv[c + 2];
                a3 += pw2[o * C + c + 3] * xv[c + 3];
            }
            p[o] = ((a0 + a1) + (a2 + a3)) * 0.125f;
        }
    }

    // ---- online-softmax over K with y accumulation ----
    float m = -1e30f, ssum = 0.f;
    float y[C];
    #pragma unroll
    for (int c = 0; c < C; c++) y[c] = 0.f;

    for (int k = 0; k < K; k++) {
        float s0 = 0.f, s1 = 0.f, s2 = 0.f, s3 = 0.f;
        #pragma unroll
        for (int c = 0; c < C; c += 4) {
            s0 += p[c + 0] * mb_s[(c + 0) * K + k];
            s1 += p[c + 1] * mb_s[(c + 1) * K + k];
            s2 += p[c + 2] * mb_s[(c + 2) * K + k];
            s3 += p[c + 3] * mb_s[(c + 3) * K + k];
        }
        float sc = (s0 + s1) + (s2 + s3);
        if (sc > m) {
            float f = __expf(m - sc);   // first iter: exp(-inf) = 0
            ssum *= f;
            #pragma unroll
            for (int c = 0; c < C; c++) y[c] *= f;
            m = sc;
        }
        float e = __expf(sc - m);
        ssum += e;
        #pragma unroll
        for (int c = 0; c < C; c++) y[c] += e * mb_s[c * K + k];
    }

    const float inv = 1.f / ssum;
    #pragma unroll
    for (int c = 0; c < C; c++) y[c] *= inv;

    // ---- wz @ y + bias + residual ----
    float* ob = out + (size_t)b * C * HW + tok;
    #pragma unroll 4
    for (int o = 0; o < C; o++) {
        float a0 = wzb_s[o], a1 = 0.f, a2 = 0.f, a3 = 0.f;
        #pragma unroll
        for (int c = 0; c < C; c += 4) {
            a0 += wz_s[o * C + c + 0] * y[c + 0];
            a1 += wz_s[o * C + c + 1] * y[c + 1];
            a2 += wz_s[o * C + c + 2] * y[c + 2];
            a3 += wz_s[o * C + c + 3] * y[c + 3];
        }
        ob[(size_t)o * HW] = ((a0 + a1) + (a2 + a3)) + xb[(size_t)o * HW];
    }
}

// ---------------------------------------------------------------------------
extern "C" void kernel_launch(void* const* d_in, const int* in_sizes, int n_in,
                              void* d_out, int out_size) {
    const float* x     = (const float*)d_in[0];
    const float* mb    = (const float*)d_in[1];
    const float* phi_w = (const float*)d_in[2];
    const float* phi_b = (const float*)d_in[3];
    const float* gn_w  = (const float*)d_in[4];
    const float* gn_b  = (const float*)d_in[5];
    const float* wz_w  = (const float*)d_in[6];
    const float* wz_b  = (const float*)d_in[7];
    float* out = (float*)d_out;

    const int smem_bytes = (C * K + 2 * C * C + 4 * C) * sizeof(float);  // 164,864 B
    cudaFuncSetAttribute(fused_vq_kernel,
                         cudaFuncAttributeMaxDynamicSharedMemorySize, smem_bytes);

    gn_stats_kernel<<<NB * NG, 256>>>(x);

    dim3 grid(HW / TPB, NB);
    fused_vq_kernel<<<grid, TPB, smem_bytes>>>(x, mb, phi_w, phi_b, gn_w, gn_b,
                                               wz_w, wz_b, out);
}

// round 2
// speedup vs baseline: 1.0003x; 1.0003x over previous
#include <cuda_runtime.h>

#define NB 10       // n*t batches
#define C  64       // channels
#define HW 16384    // 128*128 spatial
#define K  512      // codebook size
#define NG 32       // groups
#define CPG 2       // channels per group
#define TPB 256     // threads per block (1 token each)

// Scratch for GroupNorm statistics (no cudaMalloc allowed).
__device__ float g_mean[NB * NG];
__device__ float g_rstd[NB * NG];

// ---------------------------------------------------------------------------
// Kernel 1: GroupNorm statistics. One block per (batch, group).
// Each group's data is 2*16384 = 32768 CONTIGUOUS floats in (B,C,H,W) layout.
// ---------------------------------------------------------------------------
__global__ void gn_stats_kernel(const float* __restrict__ x) {
    int bg = blockIdx.x;  // 0..319  == b*NG + g
    const float4* p = (const float4*)(x + (size_t)bg * (CPG * HW));
    const int n4 = (CPG * HW) / 4;  // 8192

    float s = 0.f, ss = 0.f;
    #pragma unroll 4
    for (int i = threadIdx.x; i < n4; i += blockDim.x) {
        float4 v = p[i];
        s  += (v.x + v.y) + (v.z + v.w);
        ss += (v.x * v.x + v.y * v.y) + (v.z * v.z + v.w * v.w);
    }
    // warp reduce
    #pragma unroll
    for (int o = 16; o; o >>= 1) {
        s  += __shfl_xor_sync(0xFFFFFFFFu, s, o);
        ss += __shfl_xor_sync(0xFFFFFFFFu, ss, o);
    }
    __shared__ float sm1[8], sm2[8];
    int w = threadIdx.x >> 5, l = threadIdx.x & 31;
    if (l == 0) { sm1[w] = s; sm2[w] = ss; }
    __syncthreads();
    if (threadIdx.x == 0) {
        float ts = 0.f, tss = 0.f;
        #pragma unroll
        for (int i = 0; i < 8; i++) { ts += sm1[i]; tss += sm2[i]; }
        const float inv = 1.f / (float)(CPG * HW);
        float mean = ts * inv;
        float var  = tss * inv - mean * mean;   // biased var, matches jnp.var
        g_mean[bg] = mean;
        g_rstd[bg] = rsqrtf(var + 1e-6f);
    }
}

// ---------------------------------------------------------------------------
// Kernel 2: fused GN-fold -> phi -> soft-VQ softmax attention -> wz + residual
// One thread per token; codebook + folded weights resident in smem.
// ---------------------------------------------------------------------------
__global__ __launch_bounds__(TPB, 1)
void fused_vq_kernel(const float* __restrict__ x,
                     const float* __restrict__ mb,
                     const float* __restrict__ phi_w,
                     const float* __restrict__ phi_b,
                     const float* __restrict__ gn_w,
                     const float* __restrict__ gn_b,
                     const float* __restrict__ wz_w,
                     const float* __restrict__ wz_b,
                     float* __restrict__ out) {
    extern __shared__ float smem[];
    float* mb_s  = smem;             // C*K   = 32768 floats
    float* pw2   = mb_s + C * K;     // C*C   = 4096  (phi_w with GN scale folded)
    float* wz_s  = pw2 + C * C;      // C*C   = 4096
    float* bias2 = wz_s + C * C;     // C     (phi bias with GN shift folded)
    float* wzb_s = bias2 + C;        // C
    float* scA   = wzb_s + C;        // C
    float* shB   = scA + C;          // C

    const int b   = blockIdx.y;
    const int tid = threadIdx.x;

    // ---- fold GroupNorm affine into per-channel scale/shift ----
    if (tid < C) {
        int g = tid >> 1;                    // CPG = 2
        float mean = g_mean[b * NG + g];
        float rstd = g_rstd[b * NG + g];
        float a = rstd * gn_w[tid];
        scA[tid] = a;
        shB[tid] = gn_b[tid] - mean * a;
        wzb_s[tid] = wz_b[tid];
    }
    __syncthreads();

    // ---- cooperative smem fills ----
    {
        const float4* src = (const float4*)mb;
        float4* dst = (float4*)mb_s;
        #pragma unroll
        for (int i = tid; i < (C * K) / 4; i += TPB) dst[i] = src[i];
    }
    for (int i = tid; i < C * C; i += TPB) {
        pw2[i]  = phi_w[i] * scA[i & (C - 1)];   // fold GN scale into phi
        wz_s[i] = wz_w[i];
    }
    if (tid < C) {
        float acc = phi_b[tid];
        #pragma unroll
        for (int c = 0; c < C; c++) acc += phi_w[tid * C + c] * shB[c];
        bias2[tid] = acc;                        // fold GN shift into phi bias
    }
    __syncthreads();

    const int tok = blockIdx.x * TPB + tid;
    const float* xb = x + (size_t)b * C * HW + tok;

    // ---- phi: p = pw2 @ x_token + bias2, scaled by C^-0.5 = 0.125 ----
    float p[C];
    {
        float xv[C];
        #pragma unroll
        for (int c = 0; c < C; c++) xv[c] = xb[(size_t)c * HW];  // coalesced
        #pragma unroll 4
        for (int o = 0; o < C; o++) {
            float a0 = bias2[o], a1 = 0.f, a2 = 0.f, a3 = 0.f;
            #pragma unroll
            for (int c = 0; c < C; c += 4) {
                a0 += pw2[o * C + c + 0] * xv[c + 0];
                a1 += pw2[o * C + c + 1] * xv[c + 1];
                a2 += pw2[o * C + c + 2] * xv[c + 2];
                a3 += pw2[o * C + c + 3] * xv[c + 3];
            }
            p[o] = ((a0 + a1) + (a2 + a3)) * 0.125f;
        }
    }

    // ---- online-softmax over K with y accumulation ----
    float m = -1e30f, ssum = 0.f;
    float y[C];
    #pragma unroll
    for (int c = 0; c < C; c++) y[c] = 0.f;

    for (int k = 0; k < K; k++) {
        float s0 = 0.f, s1 = 0.f, s2 = 0.f, s3 = 0.f;
        #pragma unroll
        for (int c = 0; c < C; c += 4) {
            s0 += p[c + 0] * mb_s[(c + 0) * K + k];
            s1 += p[c + 1] * mb_s[(c + 1) * K + k];
            s2 += p[c + 2] * mb_s[(c + 2) * K + k];
            s3 += p[c + 3] * mb_s[(c + 3) * K + k];
        }
        float sc = (s0 + s1) + (s2 + s3);
        if (sc > m) {
            float f = __expf(m - sc);   // first iter: exp(-inf) = 0
            ssum *= f;
            #pragma unroll
            for (int c = 0; c < C; c++) y[c] *= f;
            m = sc;
        }
        float e = __expf(sc - m);
        ssum += e;
        #pragma unroll
        for (int c = 0; c < C; c++) y[c] += e * mb_s[c * K + k];
    }

    const float inv = 1.f / ssum;
    #pragma unroll
    for (int c = 0; c < C; c++) y[c] *= inv;

    // ---- wz @ y + bias + residual ----
    float* ob = out + (size_t)b * C * HW + tok;
    #pragma unroll 4
    for (int o = 0; o < C; o++) {
        float a0 = wzb_s[o], a1 = 0.f, a2 = 0.f, a3 = 0.f;
        #pragma unroll
        for (int c = 0; c < C; c += 4) {
            a0 += wz_s[o * C + c + 0] * y[c + 0];
            a1 += wz_s[o * C + c + 1] * y[c + 1];
            a2 += wz_s[o * C + c + 2] * y[c + 2];
            a3 += wz_s[o * C + c + 3] * y[c + 3];
        }
        ob[(size_t)o * HW] = ((a0 + a1) + (a2 + a3)) + xb[(size_t)o * HW];
    }
}

// ---------------------------------------------------------------------------
extern "C" void kernel_launch(void* const* d_in, const int* in_sizes, int n_in,
                              void* d_out, int out_size) {
    const float* x     = (const float*)d_in[0];
    const float* mb    = (const float*)d_in[1];
    const float* phi_w = (const float*)d_in[2];
    const float* phi_b = (const float*)d_in[3];
    const float* gn_w  = (const float*)d_in[4];
    const float* gn_b  = (const float*)d_in[5];
    const float* wz_w  = (const float*)d_in[6];
    const float* wz_b  = (const float*)d_in[7];
    float* out = (float*)d_out;

    const int smem_bytes = (C * K + 2 * C * C + 4 * C) * sizeof(float);  // 164,864 B
    cudaFuncSetAttribute(fused_vq_kernel,
                         cudaFuncAttributeMaxDynamicSharedMemorySize, smem_bytes);

    gn_stats_kernel<<<NB * NG, 256>>>(x);

    dim3 grid(HW / TPB, NB);
    fused_vq_kernel<<<grid, TPB, smem_bytes>>>(x, mb, phi_w, phi_b, gn_w, gn_b,
                                               wz_w, wz_b, out);
}

// round 4
// speedup vs baseline: 3.5617x; 3.5606x over previous
#include <cuda_runtime.h>
#include <cuda_bf16.h>
#include <cstdint>

#define NB   10
#define C    64
#define HW   16384
#define KCB  512
#define NG   32
#define TOKT 256
#define THREADS 256

// ---- smem layout (bytes from dynamic base) ----
#define XH_OFF   0            // 256 rows x 132B (66 bf16, padded)
#define XL_OFF   33792
#define WB_OFF   67584        // 2 stages x 4 planes x 9216B (64 rows x 144B)
#define SB_OFF   141312       // sbias 512 f32
#define ZR_OFF   143360       // zrow 256 f32
#define WZB_OFF  144384       // wz_b 64 f32
#define SMEM_TOTAL 144640
// epilogue y-stage reuses [0 .. 66560): 64 rows x 260 f32

// ---------------- device-global scratch ----------------
__device__ float g_mean[NB * NG], g_rstd[NB * NG];
__device__ float g_scA[NB * C], g_bias2[NB * C];
__device__ float g_sbias[NB * KCB];
__device__ __align__(16) __nv_bfloat16 g_W2T_hi[NB * KCB * C];  // [b][k][c]
__device__ __align__(16) __nv_bfloat16 g_W2T_lo[NB * KCB * C];
__device__ __align__(16) __nv_bfloat16 g_mb2_hi[C * KCB];       // [o][k]
__device__ __align__(16) __nv_bfloat16 g_mb2_lo[C * KCB];

// ---------------- helpers ----------------
__device__ __forceinline__ uint32_t smem_u32(const void* p) {
    uint32_t a;
    asm("{ .reg .u64 t; cvta.to.shared.u64 t, %1; cvt.u32.u64 %0, t; }" : "=r"(a) : "l"(p));
    return a;
}
__device__ __forceinline__ void mma16816(float* c,
        uint32_t a0, uint32_t a1, uint32_t a2, uint32_t a3,
        uint32_t b0, uint32_t b1) {
    asm volatile(
        "mma.sync.aligned.m16n8k16.row.col.f32.bf16.bf16.f32 "
        "{%0,%1,%2,%3}, {%4,%5,%6,%7}, {%8,%9}, {%0,%1,%2,%3};"
        : "+f"(c[0]), "+f"(c[1]), "+f"(c[2]), "+f"(c[3])
        : "r"(a0), "r"(a1), "r"(a2), "r"(a3), "r"(b0), "r"(b1));
}
__device__ __forceinline__ uint32_t pack2(float a, float b) {
    __nv_bfloat162 h = __floats2bfloat162_rn(a, b);
    return *reinterpret_cast<uint32_t*>(&h);
}

// ---------------- K1: GroupNorm stats ----------------
__global__ void gn_stats_kernel(const float* __restrict__ x) {
    int bg = blockIdx.x;
    const float4* p = (const float4*)(x + (size_t)bg * (2 * HW));
    float s = 0.f, ss = 0.f;
    #pragma unroll 4
    for (int i = threadIdx.x; i < (2 * HW) / 4; i += blockDim.x) {
        float4 v = p[i];
        s  += (v.x + v.y) + (v.z + v.w);
        ss += (v.x * v.x + v.y * v.y) + (v.z * v.z + v.w * v.w);
    }
    #pragma unroll
    for (int o = 16; o; o >>= 1) {
        s  += __shfl_xor_sync(0xFFFFFFFFu, s, o);
        ss += __shfl_xor_sync(0xFFFFFFFFu, ss, o);
    }
    __shared__ float sm1[8], sm2[8];
    int w = threadIdx.x >> 5;
    if ((threadIdx.x & 31) == 0) { sm1[w] = s; sm2[w] = ss; }
    __syncthreads();
    if (threadIdx.x == 0) {
        float ts = 0.f, tss = 0.f;
        #pragma unroll
        for (int i = 0; i < 8; i++) { ts += sm1[i]; tss += sm2[i]; }
        const float inv = 1.f / (float)(2 * HW);
        float mean = ts * inv;
        float var  = tss * inv - mean * mean;
        g_mean[bg] = mean;
        g_rstd[bg] = rsqrtf(var + 1e-6f);
    }
}

// ---------------- K2: GN fold + folded phi bias ----------------
__global__ void prep0_kernel(const float* __restrict__ phi_w, const float* __restrict__ phi_b,
                             const float* __restrict__ gn_w, const float* __restrict__ gn_b) {
    int b = blockIdx.x, c = threadIdx.x;
    __shared__ float shB[C];
    int g = c >> 1;
    float a = g_rstd[b * NG + g] * gn_w[c];
    g_scA[b * C + c] = a;
    shB[c] = gn_b[c] - g_mean[b * NG + g] * a;
    __syncthreads();
    float acc = phi_b[c];
    #pragma unroll
    for (int j = 0; j < C; j++) acc += phi_w[c * C + j] * shB[j];
    g_bias2[b * C + c] = acc;
}

// ---------------- K3: W2T[b][k][c] split planes + sbias ----------------
__global__ void prep1_kernel(const float* __restrict__ phi_w, const float* __restrict__ mb) {
    int k = blockIdx.x, b = blockIdx.y, c = threadIdx.x;
    float gacc = 0.f;
    #pragma unroll
    for (int o = 0; o < C; o++) gacc += phi_w[o * C + c] * mb[o * KCB + k];
    float v = 0.125f * g_scA[b * C + c] * gacc;
    __nv_bfloat16 hi = __float2bfloat16(v);
    __nv_bfloat16 lo = __float2bfloat16(v - __bfloat162float(hi));
    g_W2T_hi[b * (KCB * C) + k * C + c] = hi;
    g_W2T_lo[b * (KCB * C) + k * C + c] = lo;

    float p = g_bias2[b * C + c] * mb[c * KCB + k];
    #pragma unroll
    for (int o = 16; o; o >>= 1) p += __shfl_xor_sync(0xFFFFFFFFu, p, o);
    __shared__ float ws[2];
    if ((c & 31) == 0) ws[c >> 5] = p;
    __syncthreads();
    if (c == 0) g_sbias[b * KCB + k] = 0.125f * (ws[0] + ws[1]);
}

// ---------------- K4: mb2[o][k] = wz_w @ mb split planes ----------------
__global__ void prep2_kernel(const float* __restrict__ wz_w, const float* __restrict__ mb) {
    int k = blockIdx.x, o = threadIdx.x;
    float acc = 0.f;
    #pragma unroll
    for (int c = 0; c < C; c++) acc += wz_w[o * C + c] * mb[c * KCB + k];
    __nv_bfloat16 hi = __float2bfloat16(acc);
    __nv_bfloat16 lo = __float2bfloat16(acc - __bfloat162float(hi));
    g_mb2_hi[o * KCB + k] = hi;
    g_mb2_lo[o * KCB + k] = lo;
}

// ---------------- weight chunk prefetch via cp.async ----------------
__device__ __forceinline__ void prefetch_chunk(int ci, int st, int b, int tid, uint32_t smb) {
    #pragma unroll
    for (int t = 0; t < 8; t++) {
        int idx = tid + t * 256;
        int plane = idx >> 9, rem = idx & 511, row = rem >> 3, seg = rem & 7;
        const __nv_bfloat16* src;
        if      (plane == 0) src = g_W2T_hi + b * (KCB * C) + (ci * 64 + row) * 64 + seg * 8;
        else if (plane == 1) src = g_W2T_lo + b * (KCB * C) + (ci * 64 + row) * 64 + seg * 8;
        else if (plane == 2) src = g_mb2_hi + row * KCB + ci * 64 + seg * 8;
        else                 src = g_mb2_lo + row * KCB + ci * 64 + seg * 8;
        uint32_t dst = smb + WB_OFF + st * 36864 + plane * 9216 + row * 144 + seg * 16;
        asm volatile("cp.async.ca.shared.global [%0], [%1], 16;" :: "r"(dst), "l"(src) : "memory");
    }
}

// ---------------- K5: main fused kernel ----------------
__global__ __launch_bounds__(THREADS, 1)
void fused_main_kernel(const float* __restrict__ x, float* __restrict__ out,
                       const float* __restrict__ wz_b) {
    extern __shared__ char S[];
    const int tid = threadIdx.x, wid = tid >> 5, lane = tid & 31;
    const int g = lane >> 2, tq = lane & 3;
    const int b = blockIdx.y;
    const int tok0 = blockIdx.x * TOKT;
    const int wtok = wid * 32;
    const uint32_t smb = smem_u32(S);

    // prefetch chunk 0 and 1 weights
    prefetch_chunk(0, 0, b, tid, smb);
    asm volatile("cp.async.commit_group;" ::: "memory");
    prefetch_chunk(1, 1, b, tid, smb);
    asm volatile("cp.async.commit_group;" ::: "memory");

    if (tid < C) ((float*)(S + WZB_OFF))[tid] = wz_b[tid];
    for (int i = tid; i < KCB; i += THREADS)
        ((float*)(S + SB_OFF))[i] = g_sbias[b * KCB + i];

    // X tile: global [c][t] -> smem split hi/lo [t][c], row pad 66 bf16 (132B)
    const float* xg = x + (size_t)b * C * HW + tok0;
    {
        __nv_bfloat16* XHp = (__nv_bfloat16*)(S + XH_OFF);
        __nv_bfloat16* XLp = (__nv_bfloat16*)(S + XL_OFF);
        #pragma unroll
        for (int it = 0; it < 16; it++) {
            int i = tid + it * 256;
            int c = i >> 6, t64 = i & 63;
            float4 v = *(const float4*)(xg + (size_t)c * HW + t64 * 4);
            float vv[4] = {v.x, v.y, v.z, v.w};
            #pragma unroll
            for (int j = 0; j < 4; j++) {
                int tk = t64 * 4 + j;
                __nv_bfloat16 h = __float2bfloat16(vv[j]);
                XHp[tk * 66 + c] = h;
                XLp[tk * 66 + c] = __float2bfloat16(vv[j] - __bfloat162float(h));
            }
        }
    }
    __syncthreads();

    // X A-fragments (held in registers for all chunks)
    uint32_t ah[2][4][4], al[2][4][4];
    #pragma unroll
    for (int mt = 0; mt < 2; mt++) {
        int r0 = wtok + mt * 16 + g;
        #pragma unroll
        for (int kt = 0; kt < 4; kt++) {
            int b0 = r0 * 132 + kt * 32 + tq * 4;
            ah[mt][kt][0] = *(const uint32_t*)(S + XH_OFF + b0);
            ah[mt][kt][1] = *(const uint32_t*)(S + XH_OFF + b0 + 8 * 132);
            ah[mt][kt][2] = *(const uint32_t*)(S + XH_OFF + b0 + 16);
            ah[mt][kt][3] = *(const uint32_t*)(S + XH_OFF + b0 + 8 * 132 + 16);
            al[mt][kt][0] = *(const uint32_t*)(S + XL_OFF + b0);
            al[mt][kt][1] = *(const uint32_t*)(S + XL_OFF + b0 + 8 * 132);
            al[mt][kt][2] = *(const uint32_t*)(S + XL_OFF + b0 + 16);
            al[mt][kt][3] = *(const uint32_t*)(S + XL_OFF + b0 + 8 * 132 + 16);
        }
    }

    float yacc[2][8][4];
    #pragma unroll
    for (int mt = 0; mt < 2; mt++)
        #pragma unroll
        for (int nt = 0; nt < 8; nt++)
            #pragma unroll
            for (int q = 0; q < 4; q++) yacc[mt][nt][q] = 0.f;
    float zacc[4] = {0.f, 0.f, 0.f, 0.f};

    for (int ci = 0; ci < 8; ci++) {
        if (ci < 7) asm volatile("cp.async.wait_group 1;" ::: "memory");
        else        asm volatile("cp.async.wait_group 0;" ::: "memory");
        __syncthreads();

        const uint32_t* Wh = (const uint32_t*)(S + WB_OFF + (ci & 1) * 36864);
        const uint32_t* Wl = Wh + 2304;
        const uint32_t* Mh = Wh + 4608;
        const uint32_t* Ml = Wh + 6912;

        // GEMM2: scores chunk [32 x 64] per warp, 3 split products
        float sc[2][8][4];
        #pragma unroll
        for (int mt = 0; mt < 2; mt++)
            #pragma unroll
            for (int nt = 0; nt < 8; nt++)
                #pragma unroll
                for (int q = 0; q < 4; q++) sc[mt][nt][q] = 0.f;

        #pragma unroll
        for (int nt = 0; nt < 8; nt++) {
            int wi0 = (nt * 8 + g) * 36 + tq;
            #pragma unroll
            for (int kt = 0; kt < 4; kt++) {
                int wi = wi0 + kt * 8;
                uint32_t bh0 = Wh[wi], bh1 = Wh[wi + 4];
                uint32_t bl0 = Wl[wi], bl1 = Wl[wi + 4];
                #pragma unroll
                for (int mt = 0; mt < 2; mt++) {
                    mma16816(sc[mt][nt], ah[mt][kt][0], ah[mt][kt][1], ah[mt][kt][2], ah[mt][kt][3], bh0, bh1);
                    mma16816(sc[mt][nt], al[mt][kt][0], al[mt][kt][1], al[mt][kt][2], al[mt][kt][3], bh0, bh1);
                    mma16816(sc[mt][nt], ah[mt][kt][0], ah[mt][kt][1], ah[mt][kt][2], ah[mt][kt][3], bl0, bl1);
                }
            }
        }

        // exp + zsum + pack into A-fragments (split hi/lo)
        uint32_t eh[2][8], eh2[2][8], el[2][8], el2[2][8];
        const float* sbp = (const float*)(S + SB_OFF) + ci * 64;
        #pragma unroll
        for (int nt = 0; nt < 8; nt++) {
            float sbx = sbp[nt * 8 + 2 * tq];
            float sby = sbp[nt * 8 + 2 * tq + 1];
            #pragma unroll
            for (int mt = 0; mt < 2; mt++) {
                float e0 = __expf(sc[mt][nt][0] + sbx);
                float e1 = __expf(sc[mt][nt][1] + sby);
                float e2 = __expf(sc[mt][nt][2] + sbx);
                float e3 = __expf(sc[mt][nt][3] + sby);
                zacc[mt * 2 + 0] += e0 + e1;
                zacc[mt * 2 + 1] += e2 + e3;
                __nv_bfloat162 h01 = __floats2bfloat162_rn(e0, e1);
                __nv_bfloat162 h23 = __floats2bfloat162_rn(e2, e3);
                eh[mt][nt]  = *reinterpret_cast<uint32_t*>(&h01);
                eh2[mt][nt] = *reinterpret_cast<uint32_t*>(&h23);
                el[mt][nt]  = pack2(e0 - __low2float(h01), e1 - __high2float(h01));
                el2[mt][nt] = pack2(e2 - __low2float(h23), e3 - __high2float(h23));
            }
        }

        // GEMM3: y += E @ mb2^T (chunk), 3 split products
        #pragma unroll
        for (int nt = 0; nt < 8; nt++) {
            int wi0 = (nt * 8 + g) * 36 + tq;
            #pragma unroll
            for (int kt = 0; kt < 4; kt++) {
                int wi = wi0 + kt * 8;
                uint32_t mh0 = Mh[wi], mh1 = Mh[wi + 4];
                uint32_t ml0 = Ml[wi], ml1 = Ml[wi + 4];
                #pragma unroll
                for (int mt = 0; mt < 2; mt++) {
                    uint32_t a0 = eh[mt][2 * kt],  a1 = eh2[mt][2 * kt];
                    uint32_t a2 = eh[mt][2 * kt + 1], a3 = eh2[mt][2 * kt + 1];
                    uint32_t l0 = el[mt][2 * kt],  l1 = el2[mt][2 * kt];
                    uint32_t l2 = el[mt][2 * kt + 1], l3 = el2[mt][2 * kt + 1];
                    mma16816(yacc[mt][nt], a0, a1, a2, a3, mh0, mh1);
                    mma16816(yacc[mt][nt], l0, l1, l2, l3, mh0, mh1);
                    mma16816(yacc[mt][nt], a0, a1, a2, a3, ml0, ml1);
                }
            }
        }

        __syncthreads();
        if (ci + 2 < 8) {
            prefetch_chunk(ci + 2, ci & 1, b, tid, smb);
            asm volatile("cp.async.commit_group;" ::: "memory");
        }
    }

    // row-sum Z: reduce over quad (t) lanes
    #pragma unroll
    for (int q = 0; q < 4; q++) {
        zacc[q] += __shfl_xor_sync(0xFFFFFFFFu, zacc[q], 1);
        zacc[q] += __shfl_xor_sync(0xFFFFFFFFu, zacc[q], 2);
    }
    float* ZRp = (float*)(S + ZR_OFF);
    if (tq == 0) {
        #pragma unroll
        for (int mt = 0; mt < 2; mt++) {
            ZRp[wtok + mt * 16 + g]     = zacc[mt * 2 + 0];
            ZRp[wtok + mt * 16 + 8 + g] = zacc[mt * 2 + 1];
        }
    }
    __syncwarp();
    float iz[4];
    #pragma unroll
    for (int mt = 0; mt < 2; mt++) {
        iz[mt * 2 + 0] = 1.f / ZRp[wtok + mt * 16 + g];
        iz[mt * 2 + 1] = 1.f / ZRp[wtok + mt * 16 + 8 + g];
    }

    // stage y to smem [o][tok] (pad 260) for coalesced output
    float* YS = (float*)S;
    #pragma unroll
    for (int mt = 0; mt < 2; mt++) {
        int r0 = wtok + mt * 16 + g;
        #pragma unroll
        for (int nt = 0; nt < 8; nt++) {
            int o0 = nt * 8 + 2 * tq;
            YS[o0 * 260 + r0]           = yacc[mt][nt][0] * iz[mt * 2];
            YS[(o0 + 1) * 260 + r0]     = yacc[mt][nt][1] * iz[mt * 2];
            YS[o0 * 260 + r0 + 8]       = yacc[mt][nt][2] * iz[mt * 2 + 1];
            YS[(o0 + 1) * 260 + r0 + 8] = yacc[mt][nt][3] * iz[mt * 2 + 1];
        }
    }
    __syncthreads();

    // final: out = y + wz_b + residual, coalesced float4
    const float* wzp = (const float*)(S + WZB_OFF);
    float* og = out + (size_t)b * C * HW + tok0;
    #pragma unroll
    for (int it = 0; it < 16; it++) {
        int i = tid + it * 256;
        int o = i >> 6, t64 = i & 63;
        float4 ys = *(const float4*)(YS + o * 260 + t64 * 4);
        float4 xr = *(const float4*)(xg + (size_t)o * HW + t64 * 4);
        float wb = wzp[o];
        float4 r;
        r.x = ys.x + xr.x + wb;
        r.y = ys.y + xr.y + wb;
        r.z = ys.z + xr.z + wb;
        r.w = ys.w + xr.w + wb;
        *(float4*)(og + (size_t)o * HW + t64 * 4) = r;
    }
}

// ---------------------------------------------------------------------------
extern "C" void kernel_launch(void* const* d_in, const int* in_sizes, int n_in,
                              void* d_out, int out_size) {
    const float* x     = (const float*)d_in[0];
    const float* mb    = (const float*)d_in[1];
    const float* phi_w = (const float*)d_in[2];
    const float* phi_b = (const float*)d_in[3];
    const float* gn_w  = (const float*)d_in[4];
    const float* gn_b  = (const float*)d_in[5];
    const float* wz_w  = (const float*)d_in[6];
    const float* wz_b  = (const float*)d_in[7];
    float* out = (float*)d_out;

    cudaFuncSetAttribute(fused_main_kernel,
                         cudaFuncAttributeMaxDynamicSharedMemorySize, SMEM_TOTAL);

    gn_stats_kernel<<<NB * NG, 256>>>(x);
    prep0_kernel<<<NB, C>>>(phi_w, phi_b, gn_w, gn_b);
    {
        dim3 g1(KCB, NB);
        prep1_kernel<<<g1, C>>>(phi_w, mb);
    }
    prep2_kernel<<<KCB, C>>>(wz_w, mb);

    dim3 grid(HW / TOKT, NB);
    fused_main_kernel<<<grid, THREADS, SMEM_TOTAL>>>(x, out, wz_b);
}